// round 1
// baseline (speedup 1.0000x reference)
#include <cuda_runtime.h>

#define Bn 16
#define Cn 20
#define Hn 512
#define Wn 512
#define HWn (Hn * Wn)
#define CHWn (Cn * HWn)
#define HMASK (Hn - 1)
#define WMASK (Wn - 1)

// Scratch (allocation-free rule: __device__ globals)
__device__ unsigned char g_a1[Bn * HWn];   // step-1 "becomes above" mask
__device__ unsigned char g_e1[Bn * HWn];   // (world1 ch0 == 3.0) flag
__device__ float         g_d1[Bn * HWn];   // world1 ch1 (density after step 1)
__device__ unsigned char g_a2[Bn * HWn];   // step-2 "becomes above" mask

// exact 0/1-coefficient blend: (1-a)(1-b)y + a*x + b*z
__device__ __forceinline__ float selv(unsigned a, unsigned b, float x, float y, float z) {
    if (a & b) return x + z;
    if (a)     return x;
    if (b)     return z;
    return y;
}

// step-1 mask (shift_w = +1): forward = [w-1], above = [h-1], fwd_above = [h-1][w-1]
__device__ __forceinline__ unsigned mask1_at(const float* __restrict__ ch0,
                                             const float* __restrict__ ch1,
                                             int h, int w) {
    int hm = (h - 1) & HMASK;
    int wm = (w - 1) & WMASK;
    float d   = ch1[h * Wn + w];
    float df  = ch1[h * Wn + wm];
    float da  = ch1[hm * Wn + w];
    float dfa = ch1[hm * Wn + wm];
    unsigned e = (ch0[h * Wn + w] == 3.0f);
    return e & (df >= d) & (da < d) & (dfa < d);
}

// Kernel A: a1 everywhere + step-1 result of channels 0/1
__global__ void kA(const float* __restrict__ world) {
    int idx = blockIdx.x * blockDim.x + threadIdx.x;   // b*HW + h*W + w
    int b = idx >> 18;
    int h = (idx >> 9) & HMASK;
    int w = idx & WMASK;
    const float* base = world + (long)b * CHWn;
    const float* ch0 = base;
    const float* ch1 = base + HWn;

    unsigned a1 = mask1_at(ch0, ch1, h, w);
    int hp = (h + 1) & HMASK;
    int hm = (h - 1) & HMASK;
    unsigned b1 = mask1_at(ch0, ch1, hp, w);   // does_become_below[h] = above[h+1]

    float e1v = selv(a1, b1, ch0[hm * Wn + w], ch0[h * Wn + w], ch0[hp * Wn + w]);
    float d1v = selv(a1, b1, ch1[hm * Wn + w], ch1[h * Wn + w], ch1[hp * Wn + w]);

    g_a1[idx] = (unsigned char)a1;
    g_e1[idx] = (unsigned char)(e1v == 3.0f);
    g_d1[idx] = d1v;
}

// Kernel B: step-2 mask (shift_w = -1): forward = [w+1], above = [h-1], fwd_above = [h-1][w+1]
__global__ void kB() {
    int idx = blockIdx.x * blockDim.x + threadIdx.x;
    int b = idx >> 18;
    int h = (idx >> 9) & HMASK;
    int w = idx & WMASK;
    const float* d1 = g_d1 + (long)b * HWn;
    int hm = (h - 1) & HMASK;
    int wp = (w + 1) & WMASK;
    float d   = d1[h * Wn + w];
    float df  = d1[h * Wn + wp];
    float da  = d1[hm * Wn + w];
    float dfa = d1[hm * Wn + wp];
    unsigned a2 = g_e1[idx] & (df >= d) & (da < d) & (dfa < d);
    g_a2[idx] = (unsigned char)a2;
}

// Kernel C: fused both-step apply. One thread = one (b,c,w) column over a 64-row chunk.
#define NCH 8
#define CHUNK (Hn / NCH)   // 64

__global__ void __launch_bounds__(256, 4) kC(const float* __restrict__ world,
                                             float* __restrict__ out) {
    int w  = blockIdx.x * blockDim.x + threadIdx.x;   // grid.x = Wn/256 = 2
    int h0 = blockIdx.y * CHUNK;                      // grid.y = NCH
    int bc = blockIdx.z;                              // grid.z = Bn*Cn = 320
    int b = bc / Cn;
    int c = bc - b * Cn;

    const float* p = world + (long)b * CHWn + (long)c * HWn;
    float*       q = out   + (long)b * CHWn + (long)c * HWn;
    const unsigned char* a1 = g_a1 + (long)b * HWn;
    const unsigned char* a2 = g_a2 + (long)b * HWn;

    // rolling windows: world0 rows h-2..h+2, a1 rows h-1..h+2, a2 rows h..h+1
    float r0 = p[((h0 - 2) & HMASK) * Wn + w];
    float r1 = p[((h0 - 1) & HMASK) * Wn + w];
    float r2 = p[h0 * Wn + w];
    float r3 = p[((h0 + 1) & HMASK) * Wn + w];
    float r4 = p[((h0 + 2) & HMASK) * Wn + w];

    unsigned m0 = a1[((h0 - 1) & HMASK) * Wn + w];
    unsigned m1 = a1[h0 * Wn + w];
    unsigned m2 = a1[((h0 + 1) & HMASK) * Wn + w];
    unsigned m3 = a1[((h0 + 2) & HMASK) * Wn + w];

    unsigned n0 = a2[h0 * Wn + w];
    unsigned n1 = a2[((h0 + 1) & HMASK) * Wn + w];

#pragma unroll 8
    for (int hh = 0; hh < CHUNK; hh++) {
        int h = h0 + hh;

        // world1 at rows h-1, h, h+1 (vertical select with step-1 masks)
        float w1m = selv(m0, m1, r0, r1, r2);
        float w1c = selv(m1, m2, r1, r2, r3);
        float w1p = selv(m2, m3, r2, r3, r4);
        // world2 at row h (vertical select with step-2 masks)
        q[h * Wn + w] = selv(n0, n1, w1m, w1c, w1p);

        // advance window (wrap via & since H is a power of two)
        r0 = r1; r1 = r2; r2 = r3; r3 = r4;
        r4 = p[((h + 3) & HMASK) * Wn + w];
        m0 = m1; m1 = m2; m2 = m3;
        m3 = a1[((h + 3) & HMASK) * Wn + w];
        n0 = n1;
        n1 = a2[((h + 2) & HMASK) * Wn + w];
    }
}

extern "C" void kernel_launch(void* const* d_in, const int* in_sizes, int n_in,
                              void* d_out, int out_size) {
    const float* world = (const float*)d_in[0];   // (16,20,512,512) fp32
    float* out = (float*)d_out;

    int nmask = Bn * HWn;                 // 4,194,304
    kA<<<nmask / 256, 256>>>(world);
    kB<<<nmask / 256, 256>>>();

    dim3 grid(Wn / 256, NCH, Bn * Cn);    // (2, 8, 320)
    kC<<<grid, 256>>>(world, out);
}

// round 2
// speedup vs baseline: 1.0258x; 1.0258x over previous
#include <cuda_runtime.h>

#define Bn 16
#define Cn 20
#define Hn 512
#define Wn 512
#define W4n (Wn / 4)
#define HWn (Hn * Wn)
#define HW4n (Hn * W4n)
#define CHWn (Cn * HWn)
#define HMASK (Hn - 1)
#define W4MASK (W4n - 1)

// Scratch (__device__ globals per allocation-free rule)
__device__ unsigned g_a1[Bn * HW4n];   // step-1 mask, 4 pixels/word (1 byte each)
__device__ unsigned g_e1[Bn * HW4n];   // (world1 ch0 == 3) flag, packed
__device__ float4   g_d1[Bn * HW4n];   // world1 ch1 (density after step 1)
__device__ unsigned g_m [Bn * HW4n];   // packed: bit0 = a1, bit1 = a2, per byte

// exact 0/1-coefficient blend: (1-a)(1-b)y + a*x + b*z  (a,b nonzero == set)
__device__ __forceinline__ float selv(unsigned a, unsigned b, float x, float y, float z) {
    if (a & b) return x + z;
    if (a)     return x;
    if (b)     return z;
    return y;
}

__device__ __forceinline__ unsigned cmp3(float d, float df, float da, float dfa) {
    return (unsigned)(df >= d) & (unsigned)(da < d) & (unsigned)(dfa < d);
}

// ---------------- Kernel A: step-1 mask + step-1 ch0/ch1, 4-wide ----------------
// per lane: dm=ch1[hm][w], d=ch1[h][w], dp=ch1[hp][w];
//           dfm/dfc/dfp = ch1[row][w-1]; e0m/e0c/e0p = ch0[row][w]
__device__ __forceinline__ void kA_lane(
    float dm, float d, float dp, float dfm, float dfc, float dfp,
    float e0m, float e0c, float e0p,
    unsigned& a1, unsigned& e1, float& d1)
{
    a1 = (unsigned)(e0c == 3.0f) & cmp3(d, dfc, dm, dfm);
    unsigned b1 = (unsigned)(e0p == 3.0f) & cmp3(dp, dfp, d, dfc);
    float e1v = selv(a1, b1, e0m, e0c, e0p);
    d1        = selv(a1, b1, dm,  d,   dp);
    e1 = (unsigned)(e1v == 3.0f);
}

__global__ void kA(const float* __restrict__ world) {
    int idx = blockIdx.x * blockDim.x + threadIdx.x;   // b*H*W4 + h*W4 + w4
    int w4 = idx & W4MASK;
    int h  = (idx >> 7) & HMASK;
    int b  = idx >> 16;
    int hm = (h - 1) & HMASK, hp = (h + 1) & HMASK;
    int w4m = (w4 - 1) & W4MASK;

    const float4* c0 = (const float4*)(world + (long)b * CHWn);
    const float4* c1 = c0 + HW4n;

    float4 c1m = c1[hm * W4n + w4], c1c = c1[h * W4n + w4], c1p = c1[hp * W4n + w4];
    float4 c1mP = c1[hm * W4n + w4m], c1cP = c1[h * W4n + w4m], c1pP = c1[hp * W4n + w4m];
    float4 c0m = c0[hm * W4n + w4], c0c = c0[h * W4n + w4], c0p = c0[hp * W4n + w4];

    unsigned a1w = 0, e1w = 0;
    float4 d1v;
    unsigned a, e; float dd;

    kA_lane(c1m.x, c1c.x, c1p.x, c1mP.w, c1cP.w, c1pP.w, c0m.x, c0c.x, c0p.x, a, e, dd);
    a1w |= a; e1w |= e; d1v.x = dd;
    kA_lane(c1m.y, c1c.y, c1p.y, c1m.x, c1c.x, c1p.x, c0m.y, c0c.y, c0p.y, a, e, dd);
    a1w |= a << 8; e1w |= e << 8; d1v.y = dd;
    kA_lane(c1m.z, c1c.z, c1p.z, c1m.y, c1c.y, c1p.y, c0m.z, c0c.z, c0p.z, a, e, dd);
    a1w |= a << 16; e1w |= e << 16; d1v.z = dd;
    kA_lane(c1m.w, c1c.w, c1p.w, c1m.z, c1c.z, c1p.z, c0m.w, c0c.w, c0p.w, a, e, dd);
    a1w |= a << 24; e1w |= e << 24; d1v.w = dd;

    g_a1[idx] = a1w;
    g_e1[idx] = e1w;
    g_d1[idx] = d1v;
}

// ---------------- Kernel B: step-2 mask, packed with a1 ----------------
// step-2 (shift_w=-1): forward = [w+1], above = [h-1], fwd_above = [h-1][w+1]
__global__ void kB() {
    int idx = blockIdx.x * blockDim.x + threadIdx.x;
    int w4 = idx & W4MASK;
    int h  = (idx >> 7) & HMASK;
    int b  = idx >> 16;
    int hm = (h - 1) & HMASK;
    int w4p = (w4 + 1) & W4MASK;

    const float4* d1 = g_d1 + (long)b * HW4n;
    float4 dc = d1[h * W4n + w4],  dm = d1[hm * W4n + w4];
    float4 dcN = d1[h * W4n + w4p], dmN = d1[hm * W4n + w4p];
    unsigned e1w = g_e1[idx];
    unsigned a1w = g_a1[idx];

    unsigned a2w = 0;
    a2w |= ((e1w)       & 1u) & cmp3(dc.x, dc.y, dm.x, dm.y);
    a2w |= (((e1w >> 8)  & 1u) & cmp3(dc.y, dc.z, dm.y, dm.z)) << 8;
    a2w |= (((e1w >> 16) & 1u) & cmp3(dc.z, dc.w, dm.z, dm.w)) << 16;
    a2w |= (((e1w >> 24) & 1u) & cmp3(dc.w, dcN.x, dm.w, dmN.x)) << 24;

    g_m[idx] = a1w | (a2w << 1);
}

// ---------------- Kernel C: fused two-step apply, 4-wide column sweep ----------------
#define NCH 8
#define CHUNK (Hn / NCH)   // 64

__device__ __forceinline__ float kC_lane(unsigned b0, unsigned b1, unsigned b2, unsigned b3,
                                         float r0, float r1, float r2, float r3, float r4) {
    float w1m = selv(b0 & 1u, b1 & 1u, r0, r1, r2);
    float w1c = selv(b1 & 1u, b2 & 1u, r1, r2, r3);
    float w1p = selv(b2 & 1u, b3 & 1u, r2, r3, r4);
    return selv(b1 & 2u, b2 & 2u, w1m, w1c, w1p);
}

__global__ void __launch_bounds__(128, 8) kC(const float* __restrict__ world,
                                             float* __restrict__ out) {
    int w4 = threadIdx.x;                 // 0..127
    int h0 = blockIdx.y * CHUNK;
    int bc = blockIdx.z;
    int b = bc / Cn;
    int c = bc - b * Cn;

    const float4* p = (const float4*)(world + (long)b * CHWn + (long)c * HWn);
    float4*       q = (float4*)(out + (long)b * CHWn + (long)c * HWn);
    const unsigned* mk = g_m + (long)b * HW4n;

    // rolling windows: world0 rows h-2..h+2; packed masks rows h-1..h+2
    float4 r0 = p[((h0 - 2) & HMASK) * W4n + w4];
    float4 r1 = p[((h0 - 1) & HMASK) * W4n + w4];
    float4 r2 = p[h0 * W4n + w4];
    float4 r3 = p[((h0 + 1) & HMASK) * W4n + w4];
    float4 r4 = p[((h0 + 2) & HMASK) * W4n + w4];

    unsigned m0 = mk[((h0 - 1) & HMASK) * W4n + w4];
    unsigned m1 = mk[h0 * W4n + w4];
    unsigned m2 = mk[((h0 + 1) & HMASK) * W4n + w4];
    unsigned m3 = mk[((h0 + 2) & HMASK) * W4n + w4];

#pragma unroll 4
    for (int hh = 0; hh < CHUNK; hh++) {
        int h = h0 + hh;
        float4 o;
        o.x = kC_lane(m0 & 255u, m1 & 255u, m2 & 255u, m3 & 255u, r0.x, r1.x, r2.x, r3.x, r4.x);
        o.y = kC_lane((m0 >> 8) & 255u, (m1 >> 8) & 255u, (m2 >> 8) & 255u, (m3 >> 8) & 255u,
                      r0.y, r1.y, r2.y, r3.y, r4.y);
        o.z = kC_lane((m0 >> 16) & 255u, (m1 >> 16) & 255u, (m2 >> 16) & 255u, (m3 >> 16) & 255u,
                      r0.z, r1.z, r2.z, r3.z, r4.z);
        o.w = kC_lane(m0 >> 24, m1 >> 24, m2 >> 24, m3 >> 24,
                      r0.w, r1.w, r2.w, r3.w, r4.w);
        q[h * W4n + w4] = o;

        r0 = r1; r1 = r2; r2 = r3; r3 = r4;
        r4 = p[((h + 3) & HMASK) * W4n + w4];
        m0 = m1; m1 = m2; m2 = m3;
        m3 = mk[((h + 3) & HMASK) * W4n + w4];
    }
}

extern "C" void kernel_launch(void* const* d_in, const int* in_sizes, int n_in,
                              void* d_out, int out_size) {
    const float* world = (const float*)d_in[0];   // (16,20,512,512) fp32
    float* out = (float*)d_out;

    int nvec = Bn * HW4n;                 // 1,048,576
    kA<<<nvec / 256, 256>>>(world);
    kB<<<nvec / 256, 256>>>();

    dim3 grid(1, NCH, Bn * Cn);           // (1, 8, 320)
    kC<<<grid, 128>>>(world, out);
}

// round 6
// speedup vs baseline: 1.5038x; 1.4660x over previous
#include <cuda_runtime.h>

#define Bn 16
#define Cn 20
#define Hn 512
#define Wn 512
#define W4n (Wn / 4)
#define HWn (Hn * Wn)
#define HW4n (Hn * W4n)
#define CHWn (Cn * HWn)
#define HMASK (Hn - 1)
#define W4MASK (W4n - 1)

// Scratch (__device__ globals per allocation-free rule)
__device__ unsigned g_a1[Bn * HW4n];    // step-1 mask, 1 byte/pixel (0/1)
__device__ unsigned g_e1[Bn * HW4n];    // (world1 ch0 == 3) flag, packed
__device__ float4   g_d1[Bn * HW4n];    // world1 ch1 (density after step 1)
__device__ unsigned g_code[Bn * HW4n];  // per byte: a1[h] | a1[h+1]<<1 | a2[h]<<2 | a2[h+1]<<3

// exact 0/1-coefficient blend, BRANCHLESS: (1-a)(1-b)y + a*x + b*z
__device__ __forceinline__ float selv(bool a, bool b, float x, float y, float z) {
    float t = b ? z : y;
    t = a ? x : t;
    return (a && b) ? (x + z) : t;
}

__device__ __forceinline__ unsigned cmp3(float d, float df, float da, float dfa) {
    return (unsigned)(df >= d) & (unsigned)(da < d) & (unsigned)(dfa < d);
}

// ---------------- Kernel A: step-1 mask + step-1 ch0/ch1, 4-wide ----------------
__device__ __forceinline__ void kA_lane(
    float dm, float d, float dp, float dfm, float dfc, float dfp,
    float e0m, float e0c, float e0p,
    unsigned& a1, unsigned& e1, float& d1)
{
    a1 = (unsigned)(e0c == 3.0f) & cmp3(d, dfc, dm, dfm);
    unsigned b1 = (unsigned)(e0p == 3.0f) & cmp3(dp, dfp, d, dfc);
    float e1v = selv(a1 != 0u, b1 != 0u, e0m, e0c, e0p);
    d1        = selv(a1 != 0u, b1 != 0u, dm,  d,   dp);
    e1 = (unsigned)(e1v == 3.0f);
}

__global__ void kA(const float* __restrict__ world) {
    int idx = blockIdx.x * blockDim.x + threadIdx.x;   // b<<16 | h<<7 | w4
    int w4 = idx & W4MASK;
    int h  = (idx >> 7) & HMASK;
    int b  = idx >> 16;
    int hm = (h - 1) & HMASK, hp = (h + 1) & HMASK;
    int w4m = (w4 - 1) & W4MASK;

    const float4* c0 = (const float4*)(world + (long)b * CHWn);
    const float4* c1 = c0 + HW4n;

    float4 c1m = c1[hm * W4n + w4], c1c = c1[h * W4n + w4], c1p = c1[hp * W4n + w4];
    float4 c1mP = c1[hm * W4n + w4m], c1cP = c1[h * W4n + w4m], c1pP = c1[hp * W4n + w4m];
    float4 c0m = c0[hm * W4n + w4], c0c = c0[h * W4n + w4], c0p = c0[hp * W4n + w4];

    unsigned a1w = 0, e1w = 0;
    float4 d1v;
    unsigned a, e; float dd;

    kA_lane(c1m.x, c1c.x, c1p.x, c1mP.w, c1cP.w, c1pP.w, c0m.x, c0c.x, c0p.x, a, e, dd);
    a1w |= a; e1w |= e; d1v.x = dd;
    kA_lane(c1m.y, c1c.y, c1p.y, c1m.x, c1c.x, c1p.x, c0m.y, c0c.y, c0p.y, a, e, dd);
    a1w |= a << 8; e1w |= e << 8; d1v.y = dd;
    kA_lane(c1m.z, c1c.z, c1p.z, c1m.y, c1c.y, c1p.y, c0m.z, c0c.z, c0p.z, a, e, dd);
    a1w |= a << 16; e1w |= e << 16; d1v.z = dd;
    kA_lane(c1m.w, c1c.w, c1p.w, c1m.z, c1c.z, c1p.z, c0m.w, c0c.w, c0p.w, a, e, dd);
    a1w |= a << 24; e1w |= e << 24; d1v.w = dd;

    g_a1[idx] = a1w;
    g_e1[idx] = e1w;
    g_d1[idx] = d1v;
}

// ---------------- Kernel B: step-2 mask + packed per-pixel control byte ----------------
// a2[h] = e1[h] & (d1[h][w+1]>=d1[h][w]) & (d1[h-1][w]<d1[h][w]) & (d1[h-1][w+1]<d1[h][w])
__global__ void kB() {
    int idx = blockIdx.x * blockDim.x + threadIdx.x;
    int w4 = idx & W4MASK;
    int h  = (idx >> 7) & HMASK;
    int b  = idx >> 16;
    int hm = (h - 1) & HMASK, hp = (h + 1) & HMASK;
    int w4p = (w4 + 1) & W4MASK;
    int base = b << 16;

    const float4* d1 = g_d1 + base;
    float4 dm = d1[hm * W4n + w4],  dc = d1[h * W4n + w4],  dp = d1[hp * W4n + w4];
    float4 dmN = d1[hm * W4n + w4p], dcN = d1[h * W4n + w4p], dpN = d1[hp * W4n + w4p];
    unsigned e1c = g_e1[idx];
    unsigned e1p = g_e1[base + hp * W4n + w4];
    unsigned a1c = g_a1[idx];
    unsigned a1p = g_a1[base + hp * W4n + w4];

    unsigned a2c = ((e1c)        & 1u) & cmp3(dc.x, dc.y, dm.x, dm.y);
    a2c |= (((e1c >> 8)  & 1u) & cmp3(dc.y, dc.z, dm.y, dm.z)) << 8;
    a2c |= (((e1c >> 16) & 1u) & cmp3(dc.z, dc.w, dm.z, dm.w)) << 16;
    a2c |= (((e1c >> 24) & 1u) & cmp3(dc.w, dcN.x, dm.w, dmN.x)) << 24;

    unsigned a2p = ((e1p)        & 1u) & cmp3(dp.x, dp.y, dc.x, dc.y);
    a2p |= (((e1p >> 8)  & 1u) & cmp3(dp.y, dp.z, dc.y, dc.z)) << 8;
    a2p |= (((e1p >> 16) & 1u) & cmp3(dp.z, dp.w, dc.z, dc.w)) << 16;
    a2p |= (((e1p >> 24) & 1u) & cmp3(dp.w, dpN.x, dc.w, dcN.x)) << 24;

    g_code[idx] = a1c | (a1p << 1) | (a2c << 2) | (a2p << 3);
}

// ---------------- Kernel C: fused two-step apply, rolling w1 window ----------------
#define NCH 8
#define CHUNK (Hn / NCH)   // 64

// w1 at row t (bits 0,1 of code[t]):  selv(a1[t], a1[t+1], r[t-1], r[t], r[t+1])
__device__ __forceinline__ float4 w1vec(unsigned cw, float4 a, float4 b, float4 c) {
    float4 o;
    o.x = selv(cw & 0x00000001u, cw & 0x00000002u, a.x, b.x, c.x);
    o.y = selv(cw & 0x00000100u, cw & 0x00000200u, a.y, b.y, c.y);
    o.z = selv(cw & 0x00010000u, cw & 0x00020000u, a.z, b.z, c.z);
    o.w = selv(cw & 0x01000000u, cw & 0x02000000u, a.w, b.w, c.w);
    return o;
}
// out at row h (bits 2,3 of code[h]):  selv(a2[h], a2[h+1], w1[h-1], w1[h], w1[h+1])
__device__ __forceinline__ float4 outvec(unsigned cw, float4 a, float4 b, float4 c) {
    float4 o;
    o.x = selv(cw & 0x00000004u, cw & 0x00000008u, a.x, b.x, c.x);
    o.y = selv(cw & 0x00000400u, cw & 0x00000800u, a.y, b.y, c.y);
    o.z = selv(cw & 0x00040000u, cw & 0x00080000u, a.z, b.z, c.z);
    o.w = selv(cw & 0x04000000u, cw & 0x08000000u, a.w, b.w, c.w);
    return o;
}

__global__ void __launch_bounds__(128, 8) kC(const float* __restrict__ world,
                                             float* __restrict__ out) {
    int w4 = threadIdx.x;                 // 0..127 — full row of float4
    int h0 = blockIdx.y * CHUNK;
    int bc = blockIdx.z;
    int b = bc / Cn;
    int c = bc - b * Cn;

    const float4* p = (const float4*)(world + (long)b * CHWn + (long)c * HWn);
    float4*       q = (float4*)(out + (long)b * CHWn + (long)c * HWn);
    const unsigned* ck = g_code + (b << 16);

    float4 r0 = p[((h0 - 2) & HMASK) * W4n + w4];
    float4 r1 = p[((h0 - 1) & HMASK) * W4n + w4];
    float4 r2 = p[h0 * W4n + w4];
    float4 r3 = p[((h0 + 1) & HMASK) * W4n + w4];
    float4 r4 = p[((h0 + 2) & HMASK) * W4n + w4];

    unsigned cm = ck[((h0 - 1) & HMASK) * W4n + w4];
    unsigned cc = ck[h0 * W4n + w4];
    unsigned cp = ck[((h0 + 1) & HMASK) * W4n + w4];

    float4 t0 = w1vec(cm, r0, r1, r2);   // w1[h0-1]
    float4 t1 = w1vec(cc, r1, r2, r3);   // w1[h0]
    float4 t2 = w1vec(cp, r2, r3, r4);   // w1[h0+1]

#pragma unroll 4
    for (int hh = 0; hh < CHUNK; hh++) {
        int h = h0 + hh;
        float4 rn = p[((h + 3) & HMASK) * W4n + w4];
        unsigned cn = ck[((h + 2) & HMASK) * W4n + w4];

        q[h * W4n + w4] = outvec(cc, t0, t1, t2);

        r0 = r1; r1 = r2; r2 = r3; r3 = r4; r4 = rn;
        t0 = t1; t1 = t2;
        t2 = w1vec(cn, r2, r3, r4);      // w1[h+2] over rows h+1..h+3
        cc = cp; cp = cn;
    }
}

extern "C" void kernel_launch(void* const* d_in, const int* in_sizes, int n_in,
                              void* d_out, int out_size) {
    const float* world = (const float*)d_in[0];   // (16,20,512,512) fp32
    float* out = (float*)d_out;

    int nvec = Bn * HW4n;                 // 1,048,576
    kA<<<nvec / 256, 256>>>(world);
    kB<<<nvec / 256, 256>>>();

    dim3 grid(1, NCH, Bn * Cn);           // (1, 8, 320)
    kC<<<grid, 128>>>(world, out);
}